// round 3
// baseline (speedup 1.0000x reference)
#include <cuda_runtime.h>
#include <cuda_bf16.h>
#include <cstdint>

#define B_   16
#define N_   4096
#define M_   1024
#define C1_  256
#define C2_  512
#define K1_  768
#define CO_  256
#define BNR  (B_*N_)      // 65536 rows

#define LDA  40           // bf16 elems per A smem row (32 + 8 pad)
#define LDB  264          // bf16 elems per B smem row (256 + 8 pad)
#define SMEM_BYTES ((2*128*LDA + 2*32*LDB)*2 + 3*256*4)   // 57344

// ---------------- scratch (device globals; no allocation allowed) ----------
__device__ float g_y1[BNR*CO_];
__device__ float g_y2[BNR*CO_];
__device__ float g_w[BNR*3];
__device__ int   g_idx[BNR*3];
__device__ __nv_bfloat16 g_W1hi[K1_*CO_], g_W1lo[K1_*CO_];
__device__ __nv_bfloat16 g_W2hi[CO_*CO_], g_W2lo[CO_*CO_];
__device__ float g_stats1[2*CO_], g_stats2[2*CO_];
__device__ float g_bn1a[CO_], g_bn1b[CO_], g_bn2a[CO_], g_bn2b[CO_];

// ---------------- small helpers -------------------------------------------
__device__ __forceinline__ uint32_t s2u(const void* p){
    return (uint32_t)__cvta_generic_to_shared(p);
}
__device__ __forceinline__ void ldsm4(uint32_t r[4], uint32_t a){
    asm volatile("ldmatrix.sync.aligned.m8n8.x4.shared.b16 {%0,%1,%2,%3}, [%4];\n"
        : "=r"(r[0]),"=r"(r[1]),"=r"(r[2]),"=r"(r[3]) : "r"(a));
}
__device__ __forceinline__ void ldsm4t(uint32_t r[4], uint32_t a){
    asm volatile("ldmatrix.sync.aligned.m8n8.x4.trans.shared.b16 {%0,%1,%2,%3}, [%4];\n"
        : "=r"(r[0]),"=r"(r[1]),"=r"(r[2]),"=r"(r[3]) : "r"(a));
}
__device__ __forceinline__ void mma16816(float c[4], const uint32_t a[4], const uint32_t b[2]){
    asm volatile("mma.sync.aligned.m16n8k16.row.col.f32.bf16.bf16.f32 "
        "{%0,%1,%2,%3}, {%4,%5,%6,%7}, {%8,%9}, {%0,%1,%2,%3};\n"
        : "+f"(c[0]),"+f"(c[1]),"+f"(c[2]),"+f"(c[3])
        : "r"(a[0]),"r"(a[1]),"r"(a[2]),"r"(a[3]),"r"(b[0]),"r"(b[1]));
}

// ---------------- zero stats ----------------------------------------------
__global__ void zero_kernel(){
    int t = blockIdx.x*blockDim.x + threadIdx.x;
    if (t < 2*CO_){ g_stats1[t] = 0.f; g_stats2[t] = 0.f; }
}

// ---------------- weight preconvert: W[o][c] -> Wt[k][n] split hi/lo ------
__global__ __launch_bounds__(256) void prep_kernel(const float* __restrict__ W1,
                                                   const float* __restrict__ W2){
    int t = blockIdx.x*256 + threadIdx.x;
    if (t < K1_*CO_){
        int k = t >> 8, n = t & 255;
        float v = W1[n*K1_ + k];
        __nv_bfloat16 h = __float2bfloat16_rn(v);
        g_W1hi[t] = h;
        g_W1lo[t] = __float2bfloat16_rn(v - __bfloat162float(h));
    }
    if (t < CO_*CO_){
        int k = t >> 8, n = t & 255;
        float v = W2[n*CO_ + k];
        __nv_bfloat16 h = __float2bfloat16_rn(v);
        g_W2hi[t] = h;
        g_W2lo[t] = __float2bfloat16_rn(v - __bfloat162float(h));
    }
}

// ---------------- 3-NN + weights ------------------------------------------
__global__ __launch_bounds__(256) void three_nn_kernel(const float* __restrict__ xyz1,
                                                       const float* __restrict__ xyz2){
    __shared__ float4 sq[M_];
    int b = blockIdx.y;
    for (int j = threadIdx.x; j < M_; j += 256){
        const float* p = xyz2 + ((size_t)b*M_ + j)*3;
        float x = p[0], y = p[1], z = p[2];
        sq[j] = make_float4(x, y, z, x*x + y*y + z*z);
    }
    __syncthreads();
    int n  = blockIdx.x*256 + threadIdx.x;
    int bn = b*N_ + n;
    float px = xyz1[bn*3+0], py = xyz1[bn*3+1], pz = xyz1[bn*3+2];
    float tx = -2.f*px, ty = -2.f*py, tz = -2.f*pz;
    float d0 = 3.4e38f, d1 = 3.4e38f, d2v = 3.4e38f;
    int   i0 = 0, i1 = 0, i2 = 0;
    #pragma unroll 4
    for (int j = 0; j < M_; j++){
        float4 q = sq[j];
        float d = fmaf(tx, q.x, q.w);
        d = fmaf(ty, q.y, d);
        d = fmaf(tz, q.z, d);
        if (d < d2v){
            if (d < d1){
                d2v = d1; i2 = i1;
                if (d < d0){ d1 = d0; i1 = i0; d0 = d; i0 = j; }
                else       { d1 = d;  i1 = j; }
            } else { d2v = d; i2 = j; }
        }
    }
    float psq = px*px + py*py + pz*pz;
    float a0 = fminf(fmaxf(d0 + psq, 0.f), 1e-10f);
    float a1 = fminf(fmaxf(d1 + psq, 0.f), 1e-10f);
    float a2 = fminf(fmaxf(d2v + psq, 0.f), 1e-10f);
    float v0 = 1.f/a0, v1 = 1.f/a1, v2 = 1.f/a2;
    float s  = v0 + v1 + v2;
    g_w[bn*3+0] = v0/s; g_w[bn*3+1] = v1/s; g_w[bn*3+2] = v2/s;
    g_idx[bn*3+0] = i0; g_idx[bn*3+1] = i1; g_idx[bn*3+2] = i2;
}

// ---------------- GEMM (bf16x3, m16n8k16) ---------------------------------
// MODE 0: A = [ gathered-interp(512) | points1(256) ], W1, out -> g_y1
// MODE 1: A = relu(bn1a*y1 + bn1b),              W2, out -> g_y2
template<int MODE, int KTILES>
__global__ __launch_bounds__(256) void gemm_kernel(const float* __restrict__ points1,
                                                   const float* __restrict__ points2,
                                                   const float* __restrict__ bias){
    extern __shared__ __align__(16) char smem_raw[];
    __nv_bfloat16* sAh = (__nv_bfloat16*)smem_raw;
    __nv_bfloat16* sAl = sAh + 128*LDA;
    __nv_bfloat16* sBh = sAl + 128*LDA;
    __nv_bfloat16* sBl = sBh + 32*LDB;
    float* s_bias = (float*)(sBl + 32*LDB);
    float* s_bna  = s_bias + 256;
    float* s_bnb  = s_bna  + 256;

    const int tid  = threadIdx.x;
    const int lane = tid & 31;
    const int warp = tid >> 5;
    const int wm   = warp & 1;          // 2 warp-rows of 64
    const int wn   = warp >> 1;         // 4 warp-cols of 64
    const int row0 = blockIdx.x * 128;

    s_bias[tid] = bias[tid];
    if (MODE == 1){ s_bna[tid] = g_bn1a[tid]; s_bnb[tid] = g_bn1b[tid]; }
    __syncthreads();

    const int r    = tid >> 1;          // A-tile row handled by this thread
    const int half = tid & 1;           // which 16-wide k half
    const int bn   = row0 + r;

    const float *gp0 = nullptr, *gp1 = nullptr, *gp2 = nullptr;
    const float *rowp1 = nullptr, *rowy = nullptr;
    float w0 = 0.f, w1 = 0.f, w2 = 0.f;
    if (MODE == 0){
        int bb = bn >> 12;
        int j0 = g_idx[bn*3+0], j1 = g_idx[bn*3+1], j2 = g_idx[bn*3+2];
        w0 = g_w[bn*3+0]; w1 = g_w[bn*3+1]; w2 = g_w[bn*3+2];
        size_t base = (size_t)bb * (M_*C2_);
        gp0 = points2 + base + (size_t)j0*C2_ + half*16;
        gp1 = points2 + base + (size_t)j1*C2_ + half*16;
        gp2 = points2 + base + (size_t)j2*C2_ + half*16;
        rowp1 = points1 + (size_t)bn*C1_ + half*16;
    } else {
        rowy = g_y1 + (size_t)bn*CO_ + half*16;
    }

    float acc[4][8][4];
    #pragma unroll
    for (int a = 0; a < 4; a++)
        #pragma unroll
        for (int q = 0; q < 8; q++)
            #pragma unroll
            for (int c = 0; c < 4; c++) acc[a][q][c] = 0.f;

    const __nv_bfloat16* gWh = (MODE == 0) ? g_W1hi : g_W2hi;
    const __nv_bfloat16* gWl = (MODE == 0) ? g_W1lo : g_W2lo;

    for (int kt = 0; kt < KTILES; kt++){
        // ---- A tile: 128x32 fp32 -> split bf16 hi/lo in smem ----
        float av[16];
        if (MODE == 0){
            if (kt < 16){
                int off = kt*32;
                #pragma unroll
                for (int i = 0; i < 4; i++){
                    float4 x0 = *(const float4*)(gp0 + off + i*4);
                    float4 x1 = *(const float4*)(gp1 + off + i*4);
                    float4 x2 = *(const float4*)(gp2 + off + i*4);
                    av[i*4+0] = w0*x0.x + w1*x1.x + w2*x2.x;
                    av[i*4+1] = w0*x0.y + w1*x1.y + w2*x2.y;
                    av[i*4+2] = w0*x0.z + w1*x1.z + w2*x2.z;
                    av[i*4+3] = w0*x0.w + w1*x1.w + w2*x2.w;
                }
            } else {
                int off = (kt-16)*32;
                #pragma unroll
                for (int i = 0; i < 4; i++){
                    float4 x = *(const float4*)(rowp1 + off + i*4);
                    av[i*4+0] = x.x; av[i*4+1] = x.y; av[i*4+2] = x.z; av[i*4+3] = x.w;
                }
            }
        } else {
            int off = kt*32;
            #pragma unroll
            for (int i = 0; i < 4; i++){
                float4 x = *(const float4*)(rowy + off + i*4);
                int kg = kt*32 + half*16 + i*4;
                av[i*4+0] = fmaxf(fmaf(s_bna[kg+0], x.x, s_bnb[kg+0]), 0.f);
                av[i*4+1] = fmaxf(fmaf(s_bna[kg+1], x.y, s_bnb[kg+1]), 0.f);
                av[i*4+2] = fmaxf(fmaf(s_bna[kg+2], x.z, s_bnb[kg+2]), 0.f);
                av[i*4+3] = fmaxf(fmaf(s_bna[kg+3], x.w, s_bnb[kg+3]), 0.f);
            }
        }
        uint32_t* dsth = (uint32_t*)(sAh + r*LDA + half*16);
        uint32_t* dstl = (uint32_t*)(sAl + r*LDA + half*16);
        #pragma unroll
        for (int i = 0; i < 8; i++){
            float e = av[2*i], o = av[2*i+1];
            __nv_bfloat16 eh = __float2bfloat16_rn(e);
            __nv_bfloat16 oh = __float2bfloat16_rn(o);
            __nv_bfloat16 el = __float2bfloat16_rn(e - __bfloat162float(eh));
            __nv_bfloat16 ol = __float2bfloat16_rn(o - __bfloat162float(oh));
            __nv_bfloat162 ph; ph.x = eh; ph.y = oh;
            __nv_bfloat162 pl; pl.x = el; pl.y = ol;
            dsth[i] = *(uint32_t*)&ph;
            dstl[i] = *(uint32_t*)&pl;
        }
        // ---- B tile: 32x256 bf16 hi/lo ----
        {
            const uint32_t* gh = (const uint32_t*)gWh + (size_t)kt*32*128;
            const uint32_t* gl = (const uint32_t*)gWl + (size_t)kt*32*128;
            uint32_t* sbh = (uint32_t*)sBh;
            uint32_t* sbl = (uint32_t*)sBl;
            #pragma unroll
            for (int i = 0; i < 16; i++){
                int idx2 = i*256 + tid;
                int kk = idx2 >> 7, nn2 = idx2 & 127;
                sbh[kk*(LDB/2) + nn2] = gh[kk*128 + nn2];
                sbl[kk*(LDB/2) + nn2] = gl[kk*128 + nn2];
            }
        }
        __syncthreads();
        // ---- compute: 2 k-steps of 16, 3-way split mma ----
        #pragma unroll
        for (int ks = 0; ks < 32; ks += 16){
            uint32_t ah[4][4], al[4][4];
            #pragma unroll
            for (int mi = 0; mi < 4; mi++){
                int arow = wm*64 + mi*16 + (lane & 15);
                int acol = ks + ((lane >> 4) << 3);
                ldsm4(ah[mi], s2u(sAh + arow*LDA + acol));
                ldsm4(al[mi], s2u(sAl + arow*LDA + acol));
            }
            uint32_t bh[4][4], bl[4][4];
            #pragma unroll
            for (int ng = 0; ng < 4; ng++){
                int rk = ks + (lane & 7) + (lane & 8);
                int cb = wn*64 + ng*16 + ((lane >> 4) << 3);
                ldsm4t(bh[ng], s2u(sBh + rk*LDB + cb));
                ldsm4t(bl[ng], s2u(sBl + rk*LDB + cb));
            }
            #pragma unroll
            for (int mi = 0; mi < 4; mi++){
                #pragma unroll
                for (int ni = 0; ni < 8; ni++){
                    const uint32_t* bph = &bh[ni>>1][(ni&1)*2];
                    const uint32_t* bpl = &bl[ni>>1][(ni&1)*2];
                    mma16816(acc[mi][ni], ah[mi], bph);   // hi*hi
                    mma16816(acc[mi][ni], al[mi], bph);   // lo*hi
                    mma16816(acc[mi][ni], ah[mi], bpl);   // hi*lo
                }
            }
        }
        __syncthreads();
    }
    // ---- epilogue: y = acc + bias ----
    float* yout = (MODE == 0) ? g_y1 : g_y2;
    #pragma unroll
    for (int mi = 0; mi < 4; mi++){
        int grow = row0 + wm*64 + mi*16 + (lane >> 2);
        #pragma unroll
        for (int ni = 0; ni < 8; ni++){
            int gcol = wn*64 + ni*8 + ((lane & 3) << 1);
            float bb0 = s_bias[gcol], bb1 = s_bias[gcol+1];
            float2 v;
            v.x = acc[mi][ni][0] + bb0; v.y = acc[mi][ni][1] + bb1;
            *(float2*)(yout + (size_t)grow*CO_ + gcol) = v;
            v.x = acc[mi][ni][2] + bb0; v.y = acc[mi][ni][3] + bb1;
            *(float2*)(yout + (size_t)(grow+8)*CO_ + gcol) = v;
        }
    }
}

// ---------------- per-channel stats (sum, sumsq) --------------------------
template<int L>
__global__ __launch_bounds__(256) void stats_kernel(){
    const float* y  = (L == 1) ? g_y1 : g_y2;
    float*       st = (L == 1) ? g_stats1 : g_stats2;
    int c  = threadIdx.x;
    int r0 = blockIdx.x * 256;
    float s = 0.f, q = 0.f;
    for (int rr = 0; rr < 256; rr++){
        float v = y[(size_t)(r0+rr)*CO_ + c];
        s += v;
        q  = fmaf(v, v, q);
    }
    atomicAdd(&st[c], s);
    atomicAdd(&st[CO_ + c], q);
}

template<int L>
__global__ void bnfin_kernel(const float* __restrict__ g, const float* __restrict__ beta){
    int c = threadIdx.x;
    const float* st = (L == 1) ? g_stats1 : g_stats2;
    float* pa = (L == 1) ? g_bn1a : g_bn2a;
    float* pb = (L == 1) ? g_bn1b : g_bn2b;
    const float invN = 1.f / (float)BNR;
    float mean = st[c] * invN;
    float var  = st[CO_ + c] * invN - mean*mean;
    float a = g[c] / sqrtf(var + 1e-5f);
    pa[c] = a;
    pb[c] = beta[c] - mean*a;
}

// ---------------- BN2 + relu + transpose to (b, c, n) ---------------------
__global__ void out_kernel(float* __restrict__ out){
    __shared__ float s[32][33];
    int b  = blockIdx.z;
    int n0 = blockIdx.x * 32, c0 = blockIdx.y * 32;
    int tx = threadIdx.x, ty = threadIdx.y;
    float v = g_y2[(size_t)(b*N_ + n0 + ty)*CO_ + c0 + tx];
    float a = g_bn2a[c0 + tx], bb = g_bn2b[c0 + tx];
    s[ty][tx] = fmaxf(fmaf(a, v, bb), 0.f);
    __syncthreads();
    out[(size_t)(b*CO_ + c0 + ty)*N_ + n0 + tx] = s[tx][ty];
}

// ---------------- launch ---------------------------------------------------
extern "C" void kernel_launch(void* const* d_in, const int* in_sizes, int n_in,
                              void* d_out, int out_size){
    const float* xyz1    = (const float*)d_in[0];
    const float* xyz2    = (const float*)d_in[1];
    const float* points1 = (const float*)d_in[2];
    const float* points2 = (const float*)d_in[3];
    const float* W1      = (const float*)d_in[4];
    const float* b1      = (const float*)d_in[5];
    const float* g1      = (const float*)d_in[6];
    const float* beta1   = (const float*)d_in[7];
    const float* W2      = (const float*)d_in[8];
    const float* b2      = (const float*)d_in[9];
    const float* g2      = (const float*)d_in[10];
    const float* beta2   = (const float*)d_in[11];
    float* out = (float*)d_out;

    cudaFuncSetAttribute(gemm_kernel<0,24>, cudaFuncAttributeMaxDynamicSharedMemorySize, SMEM_BYTES);
    cudaFuncSetAttribute(gemm_kernel<1,8>,  cudaFuncAttributeMaxDynamicSharedMemorySize, SMEM_BYTES);

    zero_kernel<<<1, 512>>>();
    prep_kernel<<<768, 256>>>(W1, W2);
    three_nn_kernel<<<dim3(16, 16), 256>>>(xyz1, xyz2);

    gemm_kernel<0,24><<<512, 256, SMEM_BYTES>>>(points1, points2, b1);
    stats_kernel<1><<<256, 256>>>();
    bnfin_kernel<1><<<1, 256>>>(g1, beta1);

    gemm_kernel<1,8><<<512, 256, SMEM_BYTES>>>(nullptr, nullptr, b2);
    stats_kernel<2><<<256, 256>>>();
    bnfin_kernel<2><<<1, 256>>>(g2, beta2);

    out_kernel<<<dim3(128, 8, 16), dim3(32, 32)>>>(out);
}

// round 5
// speedup vs baseline: 1.3495x; 1.3495x over previous
#include <cuda_runtime.h>
#include <cuda_bf16.h>
#include <cstdint>

#define B_   16
#define N_   4096
#define M_   1024
#define C1_  256
#define C2_  512
#define K1_  768
#define CO_  256
#define BNR  (B_*N_)      // 65536 rows

#define LDA  40           // bf16 elems per A smem row (32 + 8 pad) ; 80B = 5*16 aligned
#define LDB  136          // bf16 elems per B smem row (128 + 8 pad); 272B = 17*16 aligned

#define A_STAGE (2*128*LDA)   // hi+lo elems per stage = 10240
#define B_STAGE (2*32*LDB)    // hi+lo elems per stage = 8704
#define SMEM_ELEMS (2*A_STAGE + 2*B_STAGE)
#define SMEM_FLOATS (128 + 256 + 256 + 128 + 128)
#define SMEM_BYTES (SMEM_ELEMS*2 + SMEM_FLOATS*4)

// ---------------- scratch (device globals; no allocation allowed) ----------
__device__ float g_y1[BNR*CO_];
__device__ float g_y2[BNR*CO_];
__device__ float g_w[BNR*3];
__device__ int   g_idx[BNR*3];
__device__ __nv_bfloat16 g_W1hi[K1_*CO_], g_W1lo[K1_*CO_];
__device__ __nv_bfloat16 g_W2hi[CO_*CO_], g_W2lo[CO_*CO_];
__device__ float g_stats1[2*CO_], g_stats2[2*CO_];
__device__ float g_bn1a[CO_], g_bn1b[CO_], g_bn2a[CO_], g_bn2b[CO_];

// ---------------- small helpers -------------------------------------------
__device__ __forceinline__ uint32_t s2u(const void* p){
    return (uint32_t)__cvta_generic_to_shared(p);
}
__device__ __forceinline__ void ldsm4(uint32_t r[4], uint32_t a){
    asm volatile("ldmatrix.sync.aligned.m8n8.x4.shared.b16 {%0,%1,%2,%3}, [%4];\n"
        : "=r"(r[0]),"=r"(r[1]),"=r"(r[2]),"=r"(r[3]) : "r"(a));
}
__device__ __forceinline__ void ldsm4t(uint32_t r[4], uint32_t a){
    asm volatile("ldmatrix.sync.aligned.m8n8.x4.trans.shared.b16 {%0,%1,%2,%3}, [%4];\n"
        : "=r"(r[0]),"=r"(r[1]),"=r"(r[2]),"=r"(r[3]) : "r"(a));
}
__device__ __forceinline__ void mma16816(float c[4], const uint32_t a[4], const uint32_t b[2]){
    asm volatile("mma.sync.aligned.m16n8k16.row.col.f32.bf16.bf16.f32 "
        "{%0,%1,%2,%3}, {%4,%5,%6,%7}, {%8,%9}, {%0,%1,%2,%3};\n"
        : "+f"(c[0]),"+f"(c[1]),"+f"(c[2]),"+f"(c[3])
        : "r"(a[0]),"r"(a[1]),"r"(a[2]),"r"(a[3]),"r"(b[0]),"r"(b[1]));
}
__device__ __forceinline__ void cpasync16(uint32_t dst, const void* src){
    asm volatile("cp.async.cg.shared.global [%0], [%1], 16;\n" :: "r"(dst), "l"(src));
}
__device__ __forceinline__ void cp_commit(){ asm volatile("cp.async.commit_group;\n"); }
__device__ __forceinline__ void cp_wait0(){ asm volatile("cp.async.wait_group 0;\n"); }

// ---------------- zero stats ----------------------------------------------
__global__ void zero_kernel(){
    int t = blockIdx.x*blockDim.x + threadIdx.x;
    if (t < 2*CO_){ g_stats1[t] = 0.f; g_stats2[t] = 0.f; }
}

// ---------------- weight preconvert: W[o][c] -> Wt[k][n] split hi/lo ------
__global__ __launch_bounds__(256) void prep_kernel(const float* __restrict__ W1,
                                                   const float* __restrict__ W2){
    int t = blockIdx.x*256 + threadIdx.x;
    if (t < K1_*CO_){
        int k = t >> 8, n = t & 255;
        float v = W1[n*K1_ + k];
        __nv_bfloat16 h = __float2bfloat16_rn(v);
        g_W1hi[t] = h;
        g_W1lo[t] = __float2bfloat16_rn(v - __bfloat162float(h));
    }
    if (t < CO_*CO_){
        int k = t >> 8, n = t & 255;
        float v = W2[n*CO_ + k];
        __nv_bfloat16 h = __float2bfloat16_rn(v);
        g_W2hi[t] = h;
        g_W2lo[t] = __float2bfloat16_rn(v - __bfloat162float(h));
    }
}

// ---------------- 3-NN + weights ------------------------------------------
__global__ __launch_bounds__(256) void three_nn_kernel(const float* __restrict__ xyz1,
                                                       const float* __restrict__ xyz2){
    __shared__ float4 sq[M_];
    int b = blockIdx.y;
    for (int j = threadIdx.x; j < M_; j += 256){
        const float* p = xyz2 + ((size_t)b*M_ + j)*3;
        float x = p[0], y = p[1], z = p[2];
        sq[j] = make_float4(x, y, z, x*x + y*y + z*z);
    }
    __syncthreads();
    int n  = blockIdx.x*256 + threadIdx.x;
    int bn = b*N_ + n;
    float px = xyz1[bn*3+0], py = xyz1[bn*3+1], pz = xyz1[bn*3+2];
    float tx = -2.f*px, ty = -2.f*py, tz = -2.f*pz;
    float d0 = 3.4e38f, d1 = 3.4e38f, d2v = 3.4e38f;
    int   i0 = 0, i1 = 0, i2 = 0;
    #pragma unroll 4
    for (int j = 0; j < M_; j++){
        float4 q = sq[j];
        float d = fmaf(tx, q.x, q.w);
        d = fmaf(ty, q.y, d);
        d = fmaf(tz, q.z, d);
        if (d < d2v){
            if (d < d1){
                d2v = d1; i2 = i1;
                if (d < d0){ d1 = d0; i1 = i0; d0 = d; i0 = j; }
                else       { d1 = d;  i1 = j; }
            } else { d2v = d; i2 = j; }
        }
    }
    float psq = px*px + py*py + pz*pz;
    float a0 = fminf(fmaxf(d0 + psq, 0.f), 1e-10f);
    float a1 = fminf(fmaxf(d1 + psq, 0.f), 1e-10f);
    float a2 = fminf(fmaxf(d2v + psq, 0.f), 1e-10f);
    float v0 = 1.f/a0, v1 = 1.f/a1, v2 = 1.f/a2;
    float s  = v0 + v1 + v2;
    g_w[bn*3+0] = v0/s; g_w[bn*3+1] = v1/s; g_w[bn*3+2] = v2/s;
    g_idx[bn*3+0] = i0; g_idx[bn*3+1] = i1; g_idx[bn*3+2] = i2;
}

// ---------------- pipelined GEMM (bf16x3, m16n8k16) ------------------------
// Block tile 128x128, 512 threads (warp grid 4x4, warp tile 32x32), 2-stage
// double buffer. Stats (sum, sumsq per output channel) fused into epilogue.
// MODE 0: A = [ gathered-interp(512) | points1(256) ], W1, out -> g_y1
// MODE 1: A = relu(bn1a*y1 + bn1b),                    W2, out -> g_y2
template<int MODE, int KTILES>
__global__ __launch_bounds__(512) void gemm_kernel(const float* __restrict__ points1,
                                                   const float* __restrict__ points2,
                                                   const float* __restrict__ bias){
    extern __shared__ __align__(16) char smem_raw[];
    __nv_bfloat16* sA = (__nv_bfloat16*)smem_raw;             // [2][hi/lo][128*LDA]
    __nv_bfloat16* sB = sA + 2*A_STAGE;                       // [2][hi/lo][32*LDB]
    float* s_bias = (float*)(sB + 2*B_STAGE);
    float* s_bna  = s_bias + 128;
    float* s_bnb  = s_bna + 256;
    float* s_sum  = s_bnb + 256;
    float* s_sq   = s_sum + 128;

    const int tid  = threadIdx.x;
    const int lane = tid & 31;
    const int warp = tid >> 5;
    const int wm   = warp & 3;            // 4 warp-rows of 32
    const int wn   = warp >> 2;           // 4 warp-cols of 32
    const int mb   = blockIdx.x >> 1;
    const int nb   = blockIdx.x & 1;
    const int row0 = mb * 128;
    const int col0 = nb * 128;

    if (tid < 128){ s_bias[tid] = bias[col0 + tid]; s_sum[tid] = 0.f; s_sq[tid] = 0.f; }
    if (MODE == 1 && tid < 256){ s_bna[tid] = g_bn1a[tid]; s_bnb[tid] = g_bn1b[tid]; }
    __syncthreads();

    const int r    = tid >> 2;            // A row handled by this thread (0..127)
    const int seg  = tid & 3;             // 8-elem segment within 32-k tile
    const int bn   = row0 + r;

    const float *gp0 = nullptr, *gp1 = nullptr, *gp2 = nullptr;
    const float *rowp1 = nullptr, *rowy = nullptr;
    float w0 = 0.f, w1 = 0.f, w2 = 0.f;
    if (MODE == 0){
        int bb = bn >> 12;
        int j0 = g_idx[bn*3+0], j1 = g_idx[bn*3+1], j2 = g_idx[bn*3+2];
        w0 = g_w[bn*3+0]; w1 = g_w[bn*3+1]; w2 = g_w[bn*3+2];
        size_t base = (size_t)bb * (M_*C2_) + seg*8;
        gp0 = points2 + base + (size_t)j0*C2_;
        gp1 = points2 + base + (size_t)j1*C2_;
        gp2 = points2 + base + (size_t)j2*C2_;
        rowp1 = points1 + (size_t)bn*C1_ + seg*8;
    } else {
        rowy = g_y1 + (size_t)bn*CO_ + seg*8;
    }

    const __nv_bfloat16* gWh = (MODE == 0) ? g_W1hi : g_W2hi;
    const __nv_bfloat16* gWl = (MODE == 0) ? g_W1lo : g_W2lo;

    // B cp.async source/dest decomposition: 512 chunks of 16B per matrix
    const int brow = tid >> 4;            // 0..31
    const int bcol = tid & 15;            // 0..15 (x8 elems)
    const uint32_t sBu = s2u(sB);

    float acc[2][4][4];
    #pragma unroll
    for (int a = 0; a < 2; a++)
        #pragma unroll
        for (int q = 0; q < 4; q++)
            #pragma unroll
            for (int c = 0; c < 4; c++) acc[a][q][c] = 0.f;

    float pr[24];

    // ---- helpers (inlined by compiler) ----
    auto loadA = [&](int kt){
        if (MODE == 0){
            if (kt < 16){
                int off = kt*32;
                *(float4*)(pr+ 0) = *(const float4*)(gp0 + off);
                *(float4*)(pr+ 4) = *(const float4*)(gp0 + off + 4);
                *(float4*)(pr+ 8) = *(const float4*)(gp1 + off);
                *(float4*)(pr+12) = *(const float4*)(gp1 + off + 4);
                *(float4*)(pr+16) = *(const float4*)(gp2 + off);
                *(float4*)(pr+20) = *(const float4*)(gp2 + off + 4);
            } else {
                int off = (kt-16)*32;
                *(float4*)(pr+ 0) = *(const float4*)(rowp1 + off);
                *(float4*)(pr+ 4) = *(const float4*)(rowp1 + off + 4);
            }
        } else {
            int off = kt*32;
            *(float4*)(pr+ 0) = *(const float4*)(rowy + off);
            *(float4*)(pr+ 4) = *(const float4*)(rowy + off + 4);
        }
    };
    auto cpB = [&](int kt, int stage){
        const __nv_bfloat16* srch = gWh + (size_t)kt*32*CO_ + brow*CO_ + col0 + bcol*8;
        const __nv_bfloat16* srcl = gWl + (size_t)kt*32*CO_ + brow*CO_ + col0 + bcol*8;
        uint32_t dsth = sBu + (uint32_t)(stage*B_STAGE + brow*LDB + bcol*8)*2;
        cpasync16(dsth, srch);
        cpasync16(dsth + 32*LDB*2, srcl);
    };
    auto convA = [&](int kt, int stage){
        float av[8];
        if (MODE == 0){
            if (kt < 16){
                #pragma unroll
                for (int i = 0; i < 8; i++)
                    av[i] = w0*pr[i] + w1*pr[8+i] + w2*pr[16+i];
            } else {
                #pragma unroll
                for (int i = 0; i < 8; i++) av[i] = pr[i];
            }
        } else {
            int kg = kt*32 + seg*8;
            #pragma unroll
            for (int i = 0; i < 8; i++)
                av[i] = fmaxf(fmaf(s_bna[kg+i], pr[i], s_bnb[kg+i]), 0.f);
        }
        uint32_t* dsth = (uint32_t*)(sA + stage*A_STAGE + r*LDA + seg*8);
        uint32_t* dstl = (uint32_t*)(sA + stage*A_STAGE + 128*LDA + r*LDA + seg*8);
        #pragma unroll
        for (int i = 0; i < 4; i++){
            float e = av[2*i], o = av[2*i+1];
            __nv_bfloat16 eh = __float2bfloat16_rn(e);
            __nv_bfloat16 oh = __float2bfloat16_rn(o);
            __nv_bfloat16 el = __float2bfloat16_rn(e - __bfloat162float(eh));
            __nv_bfloat16 ol = __float2bfloat16_rn(o - __bfloat162float(oh));
            __nv_bfloat162 ph; ph.x = eh; ph.y = oh;
            __nv_bfloat162 pl; pl.x = el; pl.y = ol;
            dsth[i] = *(uint32_t*)&ph;
            dstl[i] = *(uint32_t*)&pl;
        }
    };
    auto compute = [&](int stage){
        const __nv_bfloat16* pAh = sA + stage*A_STAGE;
        const __nv_bfloat16* pAl = pAh + 128*LDA;
        const __nv_bfloat16* pBh = sB + stage*B_STAGE;
        const __nv_bfloat16* pBl = pBh + 32*LDB;
        #pragma unroll
        for (int ks = 0; ks < 32; ks += 16){
            uint32_t ah[2][4], al[2][4];
            #pragma unroll
            for (int mi = 0; mi < 2; mi++){
                int arow = wm*32 + mi*16 + (lane & 15);
                int acol = ks + ((lane >> 4) << 3);
                ldsm4(ah[mi], s2u(pAh + arow*LDA + acol));
                ldsm4(al[mi], s2u(pAl + arow*LDA + acol));
            }
            uint32_t bh[2][4], bl[2][4];
            int rk = ks + (lane & 7) + (lane & 8);
            #pragma unroll
            for (int g = 0; g < 2; g++){
                int cb = wn*32 + g*16 + ((lane >> 4) << 3);
                ldsm4t(bh[g], s2u(pBh + rk*LDB + cb));
                ldsm4t(bl[g], s2u(pBl + rk*LDB + cb));
            }
            #pragma unroll
            for (int mi = 0; mi < 2; mi++)
                #pragma unroll
                for (int g = 0; g < 2; g++)
                    #pragma unroll
                    for (int sub = 0; sub < 2; sub++){
                        int ni = g*2 + sub;
                        mma16816(acc[mi][ni], ah[mi], &bh[g][sub*2]);   // hi*hi
                        mma16816(acc[mi][ni], al[mi], &bh[g][sub*2]);   // lo*hi
                        mma16816(acc[mi][ni], ah[mi], &bl[g][sub*2]);   // hi*lo
                    }
        }
    };

    // ---- prologue ----
    loadA(0);
    cpB(0, 0);
    cp_commit();
    convA(0, 0);
    cp_wait0();
    __syncthreads();

    // ---- main loop ----
    for (int kt = 0; kt < KTILES; kt++){
        int cur = kt & 1, nxt = cur ^ 1;
        if (kt + 1 < KTILES){
            loadA(kt + 1);
            cpB(kt + 1, nxt);
            cp_commit();
        }
        compute(cur);
        if (kt + 1 < KTILES) convA(kt + 1, nxt);
        cp_wait0();
        __syncthreads();
    }

    // ---- epilogue: y = acc + bias, fused per-channel stats ----
    float* yout = (MODE == 0) ? g_y1 : g_y2;
    float* gst  = (MODE == 0) ? g_stats1 : g_stats2;
    #pragma unroll
    for (int ni = 0; ni < 4; ni++){
        int lc = wn*32 + ni*8 + ((lane & 3) << 1);
        int gc = col0 + lc;
        float b0 = s_bias[lc], b1 = s_bias[lc+1];
        float sum0 = 0.f, sq0 = 0.f, sum1 = 0.f, sq1 = 0.f;
        #pragma unroll
        for (int mi = 0; mi < 2; mi++){
            int gr = row0 + wm*32 + mi*16 + (lane >> 2);
            float v0 = acc[mi][ni][0] + b0;
            float v1 = acc[mi][ni][1] + b1;
            float v2 = acc[mi][ni][2] + b0;
            float v3 = acc[mi][ni][3] + b1;
            float2 p;
            p.x = v0; p.y = v1;
            *(float2*)(yout + (size_t)gr*CO_ + gc) = p;
            p.x = v2; p.y = v3;
            *(float2*)(yout + (size_t)(gr+8)*CO_ + gc) = p;
            sum0 += v0 + v2;  sq0 = fmaf(v0, v0, fmaf(v2, v2, sq0));
            sum1 += v1 + v3;  sq1 = fmaf(v1, v1, fmaf(v3, v3, sq1));
        }
        atomicAdd(&s_sum[lc],   sum0);
        atomicAdd(&s_sq[lc],    sq0);
        atomicAdd(&s_sum[lc+1], sum1);
        atomicAdd(&s_sq[lc+1],  sq1);
    }
    __syncthreads();
    if (tid < 128){
        atomicAdd(&gst[col0 + tid],        s_sum[tid]);
        atomicAdd(&gst[CO_ + col0 + tid],  s_sq[tid]);
    }
}

// ---------------- BN finalize ---------------------------------------------
template<int L>
__global__ void bnfin_kernel(const float* __restrict__ g, const float* __restrict__ beta){
    int c = threadIdx.x;
    const float* st = (L == 1) ? g_stats1 : g_stats2;
    float* pa = (L == 1) ? g_bn1a : g_bn2a;
    float* pb = (L == 1) ? g_bn1b : g_bn2b;
    const float invN = 1.f / (float)BNR;
    float mean = st[c] * invN;
    float var  = st[CO_ + c] * invN - mean*mean;
    float a = g[c] / sqrtf(var + 1e-5f);
    pa[c] = a;
    pb[c] = beta[c] - mean*a;
}

// ---------------- BN2 + relu + transpose to (b, c, n) ---------------------
__global__ void out_kernel(float* __restrict__ out){
    __shared__ float s[32][33];
    int b  = blockIdx.z;
    int n0 = blockIdx.x * 32, c0 = blockIdx.y * 32;
    int tx = threadIdx.x, ty = threadIdx.y;
    float v = g_y2[(size_t)(b*N_ + n0 + ty)*CO_ + c0 + tx];
    float a = g_bn2a[c0 + tx], bb = g_bn2b[c0 + tx];
    s[ty][tx] = fmaxf(fmaf(a, v, bb), 0.f);
    __syncthreads();
    out[(size_t)(b*CO_ + c0 + ty)*N_ + n0 + tx] = s[tx][ty];
}

// ---------------- launch ---------------------------------------------------
extern "C" void kernel_launch(void* const* d_in, const int* in_sizes, int n_in,
                              void* d_out, int out_size){
    const float* xyz1    = (const float*)d_in[0];
    const float* xyz2    = (const float*)d_in[1];
    const float* points1 = (const float*)d_in[2];
    const float* points2 = (const float*)d_in[3];
    const float* W1      = (const float*)d_in[4];
    const float* b1      = (const float*)d_in[5];
    const float* g1      = (const float*)d_in[6];
    const float* beta1   = (const float*)d_in[7];
    const float* W2      = (const float*)d_in[8];
    const float* b2      = (const float*)d_in[9];
    const float* g2      = (const float*)d_in[10];
    const float* beta2   = (const float*)d_in[11];
    float* out = (float*)d_out;

    cudaFuncSetAttribute(gemm_kernel<0,24>, cudaFuncAttributeMaxDynamicSharedMemorySize, SMEM_BYTES);
    cudaFuncSetAttribute(gemm_kernel<1,8>,  cudaFuncAttributeMaxDynamicSharedMemorySize, SMEM_BYTES);

    zero_kernel<<<1, 512>>>();
    prep_kernel<<<768, 256>>>(W1, W2);
    three_nn_kernel<<<dim3(16, 16), 256>>>(xyz1, xyz2);

    gemm_kernel<0,24><<<1024, 512, SMEM_BYTES>>>(points1, points2, b1);
    bnfin_kernel<1><<<1, 256>>>(g1, beta1);

    gemm_kernel<1,8><<<1024, 512, SMEM_BYTES>>>(nullptr, nullptr, b2);
    bnfin_kernel<2><<<1, 256>>>(g2, beta2);

    out_kernel<<<dim3(128, 8, 16), dim3(32, 32)>>>(out);
}

// round 6
// speedup vs baseline: 1.3996x; 1.0372x over previous
#include <cuda_runtime.h>
#include <cuda_bf16.h>
#include <cstdint>

#define B_   16
#define N_   4096
#define M_   1024
#define C1_  256
#define C2_  512
#define K1_  768
#define CO_  256
#define BNR  (B_*N_)      // 65536 rows

#define LDA  40           // bf16 elems per A smem row (32 + 8 pad)
#define LDB  264          // bf16 elems per B smem row (256 + 8 pad)

#define A_STAGE (2*128*LDA)   // hi+lo elems per stage = 10240
#define B_STAGE (2*32*LDB)    // hi+lo elems per stage = 16896
#define SMEM_FLOATS (256 + 256 + 256 + 256 + 256)
#define SMEM_BYTES ((2*A_STAGE + 2*B_STAGE)*2 + SMEM_FLOATS*4)   // 113664

// ---------------- scratch (device globals; no allocation allowed) ----------
__device__ float g_y1[BNR*CO_];
__device__ float g_y2[BNR*CO_];
__device__ float g_w[BNR*3];
__device__ int   g_idx[BNR*3];
__device__ __nv_bfloat16 g_W1hi[K1_*CO_], g_W1lo[K1_*CO_];
__device__ __nv_bfloat16 g_W2hi[CO_*CO_], g_W2lo[CO_*CO_];
__device__ float g_stats1[2*CO_], g_stats2[2*CO_];
__device__ float g_bn1a[CO_], g_bn1b[CO_], g_bn2a[CO_], g_bn2b[CO_];

// ---------------- small helpers -------------------------------------------
__device__ __forceinline__ uint32_t s2u(const void* p){
    return (uint32_t)__cvta_generic_to_shared(p);
}
__device__ __forceinline__ void ldsm4(uint32_t r[4], uint32_t a){
    asm volatile("ldmatrix.sync.aligned.m8n8.x4.shared.b16 {%0,%1,%2,%3}, [%4];\n"
        : "=r"(r[0]),"=r"(r[1]),"=r"(r[2]),"=r"(r[3]) : "r"(a));
}
__device__ __forceinline__ void ldsm4t(uint32_t r[4], uint32_t a){
    asm volatile("ldmatrix.sync.aligned.m8n8.x4.trans.shared.b16 {%0,%1,%2,%3}, [%4];\n"
        : "=r"(r[0]),"=r"(r[1]),"=r"(r[2]),"=r"(r[3]) : "r"(a));
}
__device__ __forceinline__ void mma16816(float c[4], const uint32_t a[4], const uint32_t b[2]){
    asm volatile("mma.sync.aligned.m16n8k16.row.col.f32.bf16.bf16.f32 "
        "{%0,%1,%2,%3}, {%4,%5,%6,%7}, {%8,%9}, {%0,%1,%2,%3};\n"
        : "+f"(c[0]),"+f"(c[1]),"+f"(c[2]),"+f"(c[3])
        : "r"(a[0]),"r"(a[1]),"r"(a[2]),"r"(a[3]),"r"(b[0]),"r"(b[1]));
}
__device__ __forceinline__ void cpasync16(uint32_t dst, const void* src){
    asm volatile("cp.async.cg.shared.global [%0], [%1], 16;\n" :: "r"(dst), "l"(src));
}
__device__ __forceinline__ void cp_commit(){ asm volatile("cp.async.commit_group;\n"); }
__device__ __forceinline__ void cp_wait0(){ asm volatile("cp.async.wait_group 0;\n"); }

// ---------------- zero stats ----------------------------------------------
__global__ void zero_kernel(){
    int t = blockIdx.x*blockDim.x + threadIdx.x;
    if (t < 2*CO_){ g_stats1[t] = 0.f; g_stats2[t] = 0.f; }
}

// ---------------- weight preconvert: W[o][c] -> Wt[k][n] split hi/lo ------
__global__ __launch_bounds__(256) void prep_kernel(const float* __restrict__ W1,
                                                   const float* __restrict__ W2){
    int t = blockIdx.x*256 + threadIdx.x;
    if (t < K1_*CO_){
        int k = t >> 8, n = t & 255;
        float v = W1[n*K1_ + k];
        __nv_bfloat16 h = __float2bfloat16_rn(v);
        g_W1hi[t] = h;
        g_W1lo[t] = __float2bfloat16_rn(v - __bfloat162float(h));
    }
    if (t < CO_*CO_){
        int k = t >> 8, n = t & 255;
        float v = W2[n*CO_ + k];
        __nv_bfloat16 h = __float2bfloat16_rn(v);
        g_W2hi[t] = h;
        g_W2lo[t] = __float2bfloat16_rn(v - __bfloat162float(h));
    }
}

// ---------------- 3-NN + weights ------------------------------------------
__global__ __launch_bounds__(256) void three_nn_kernel(const float* __restrict__ xyz1,
                                                       const float* __restrict__ xyz2){
    __shared__ float4 sq[M_];
    int b = blockIdx.y;
    for (int j = threadIdx.x; j < M_; j += 256){
        const float* p = xyz2 + ((size_t)b*M_ + j)*3;
        float x = p[0], y = p[1], z = p[2];
        sq[j] = make_float4(x, y, z, x*x + y*y + z*z);
    }
    __syncthreads();
    int n  = blockIdx.x*256 + threadIdx.x;
    int bn = b*N_ + n;
    float px = xyz1[bn*3+0], py = xyz1[bn*3+1], pz = xyz1[bn*3+2];
    float tx = -2.f*px, ty = -2.f*py, tz = -2.f*pz;
    float d0 = 3.4e38f, d1 = 3.4e38f, d2v = 3.4e38f;
    int   i0 = 0, i1 = 0, i2 = 0;
    #pragma unroll 4
    for (int j = 0; j < M_; j++){
        float4 q = sq[j];
        float d = fmaf(tx, q.x, q.w);
        d = fmaf(ty, q.y, d);
        d = fmaf(tz, q.z, d);
        if (d < d2v){
            if (d < d1){
                d2v = d1; i2 = i1;
                if (d < d0){ d1 = d0; i1 = i0; d0 = d; i0 = j; }
                else       { d1 = d;  i1 = j; }
            } else { d2v = d; i2 = j; }
        }
    }
    float psq = px*px + py*py + pz*pz;
    float a0 = fminf(fmaxf(d0 + psq, 0.f), 1e-10f);
    float a1 = fminf(fmaxf(d1 + psq, 0.f), 1e-10f);
    float a2 = fminf(fmaxf(d2v + psq, 0.f), 1e-10f);
    float v0 = 1.f/a0, v1 = 1.f/a1, v2 = 1.f/a2;
    float s  = v0 + v1 + v2;
    g_w[bn*3+0] = v0/s; g_w[bn*3+1] = v1/s; g_w[bn*3+2] = v2/s;
    g_idx[bn*3+0] = i0; g_idx[bn*3+1] = i1; g_idx[bn*3+2] = i2;
}

// ---------------- pipelined GEMM (bf16x3, m16n8k16) ------------------------
// Block tile 128x256 (full N), 512 threads, warp grid 4x4, warp tile 32x64,
// 2-stage double buffer, A prefetch split into two batches interleaved with
// the two k16 compute halves. Stats fused into epilogue.
// MODE 0: A = [ gathered-interp(512) | points1(256) ], W1, out -> g_y1
// MODE 1: A = relu(bn1a*y1 + bn1b),                    W2, out -> g_y2
template<int MODE, int KTILES>
__global__ __launch_bounds__(512) void gemm_kernel(const float* __restrict__ points1,
                                                   const float* __restrict__ points2,
                                                   const float* __restrict__ bias){
    extern __shared__ __align__(16) char smem_raw[];
    __nv_bfloat16* sA = (__nv_bfloat16*)smem_raw;             // [2][hi/lo][128*LDA]
    __nv_bfloat16* sB = sA + 2*A_STAGE;                       // [2][hi/lo][32*LDB]
    float* s_bias = (float*)(sB + 2*B_STAGE);
    float* s_bna  = s_bias + 256;
    float* s_bnb  = s_bna + 256;
    float* s_sum  = s_bnb + 256;
    float* s_sq   = s_sum + 256;

    const int tid  = threadIdx.x;
    const int lane = tid & 31;
    const int warp = tid >> 5;
    const int wm   = warp & 3;            // 4 warp-rows of 32
    const int wn   = warp >> 2;           // 4 warp-cols of 64
    const int row0 = blockIdx.x * 128;

    if (tid < 256){
        s_bias[tid] = bias[tid]; s_sum[tid] = 0.f; s_sq[tid] = 0.f;
        if (MODE == 1){ s_bna[tid] = g_bn1a[tid]; s_bnb[tid] = g_bn1b[tid]; }
    }
    __syncthreads();

    const int r    = tid >> 2;            // A row handled by this thread (0..127)
    const int seg  = tid & 3;             // 8-elem segment within 32-k tile
    const int bn   = row0 + r;

    const float *gp0 = nullptr, *gp1 = nullptr, *gp2 = nullptr;
    const float *rowp1 = nullptr, *rowy = nullptr;
    float w0 = 0.f, w1 = 0.f, w2 = 0.f;
    if (MODE == 0){
        int bb = bn >> 12;
        int j0 = g_idx[bn*3+0], j1 = g_idx[bn*3+1], j2 = g_idx[bn*3+2];
        w0 = g_w[bn*3+0]; w1 = g_w[bn*3+1]; w2 = g_w[bn*3+2];
        size_t base = (size_t)bb * (M_*C2_) + seg*8;
        gp0 = points2 + base + (size_t)j0*C2_;
        gp1 = points2 + base + (size_t)j1*C2_;
        gp2 = points2 + base + (size_t)j2*C2_;
        rowp1 = points1 + (size_t)bn*C1_ + seg*8;
    } else {
        rowy = g_y1 + (size_t)bn*CO_ + seg*8;
    }

    const __nv_bfloat16* gWh = (MODE == 0) ? g_W1hi : g_W2hi;
    const __nv_bfloat16* gWl = (MODE == 0) ? g_W1lo : g_W2lo;

    // B cp.async: 32 rows x 256 cols hi+lo; each thread moves 2x16B hi + 2x16B lo
    const int brow = tid >> 4;                 // 0..31
    const int bco  = ((tid & 15) * 2) * 8;     // element col: 0,16,...,240
    const uint32_t sBu = s2u(sB);

    float acc[2][8][4];
    #pragma unroll
    for (int a = 0; a < 2; a++)
        #pragma unroll
        for (int q = 0; q < 8; q++)
            #pragma unroll
            for (int c = 0; c < 4; c++) acc[a][q][c] = 0.f;

    float pr[12];
    float av[8];

    auto cpB = [&](int kt, int stage){
        const __nv_bfloat16* srch = gWh + (size_t)kt*32*CO_ + brow*CO_ + bco;
        const __nv_bfloat16* srcl = gWl + (size_t)kt*32*CO_ + brow*CO_ + bco;
        uint32_t dsth = sBu + (uint32_t)(stage*B_STAGE + brow*LDB + bco)*2;
        uint32_t dstl = dsth + 32*LDB*2;
        cpasync16(dsth,      srch);
        cpasync16(dsth + 16, srch + 8);
        cpasync16(dstl,      srcl);
        cpasync16(dstl + 16, srcl + 8);
    };
    auto issueA = [&](int kt, int half){
        int off4 = half*4;
        if (MODE == 0){
            if (kt < 16){
                int off = kt*32 + off4;
                *(float4*)(pr+0) = *(const float4*)(gp0 + off);
                *(float4*)(pr+4) = *(const float4*)(gp1 + off);
                *(float4*)(pr+8) = *(const float4*)(gp2 + off);
            } else {
                int off = (kt-16)*32 + off4;
                *(float4*)(pr+0) = *(const float4*)(rowp1 + off);
            }
        } else {
            int off = kt*32 + off4;
            *(float4*)(pr+0) = *(const float4*)(rowy + off);
        }
    };
    auto combineA = [&](int kt, int half){
        float* o = av + half*4;
        if (MODE == 0){
            if (kt < 16){
                #pragma unroll
                for (int i = 0; i < 4; i++)
                    o[i] = w0*pr[i] + w1*pr[4+i] + w2*pr[8+i];
            } else {
                #pragma unroll
                for (int i = 0; i < 4; i++) o[i] = pr[i];
            }
        } else {
            int kg = kt*32 + seg*8 + half*4;
            #pragma unroll
            for (int i = 0; i < 4; i++)
                o[i] = fmaxf(fmaf(s_bna[kg+i], pr[i], s_bnb[kg+i]), 0.f);
        }
    };
    auto storeA = [&](int stage){
        uint32_t* dsth = (uint32_t*)(sA + stage*A_STAGE + r*LDA + seg*8);
        uint32_t* dstl = (uint32_t*)(sA + stage*A_STAGE + 128*LDA + r*LDA + seg*8);
        #pragma unroll
        for (int i = 0; i < 4; i++){
            float e = av[2*i], o = av[2*i+1];
            __nv_bfloat16 eh = __float2bfloat16_rn(e);
            __nv_bfloat16 oh = __float2bfloat16_rn(o);
            __nv_bfloat16 el = __float2bfloat16_rn(e - __bfloat162float(eh));
            __nv_bfloat16 ol = __float2bfloat16_rn(o - __bfloat162float(oh));
            __nv_bfloat162 ph; ph.x = eh; ph.y = oh;
            __nv_bfloat162 pl; pl.x = el; pl.y = ol;
            dsth[i] = *(uint32_t*)&ph;
            dstl[i] = *(uint32_t*)&pl;
        }
    };
    auto compute_half = [&](int stage, int ks){
        const __nv_bfloat16* pAh = sA + stage*A_STAGE;
        const __nv_bfloat16* pAl = pAh + 128*LDA;
        const __nv_bfloat16* pBh = sB + stage*B_STAGE;
        const __nv_bfloat16* pBl = pBh + 32*LDB;
        uint32_t ah[2][4], al[2][4];
        #pragma unroll
        for (int mi = 0; mi < 2; mi++){
            int arow = wm*32 + mi*16 + (lane & 15);
            int acol = ks + ((lane >> 4) << 3);
            ldsm4(ah[mi], s2u(pAh + arow*LDA + acol));
            ldsm4(al[mi], s2u(pAl + arow*LDA + acol));
        }
        int rk = ks + (lane & 7) + (lane & 8);
        #pragma unroll
        for (int g = 0; g < 4; g++){
            uint32_t bh[4], bl[4];
            int cb = wn*64 + g*16 + ((lane >> 4) << 3);
            ldsm4t(bh, s2u(pBh + rk*LDB + cb));
            ldsm4t(bl, s2u(pBl + rk*LDB + cb));
            #pragma unroll
            for (int mi = 0; mi < 2; mi++)
                #pragma unroll
                for (int sub = 0; sub < 2; sub++){
                    int ni = g*2 + sub;
                    mma16816(acc[mi][ni], ah[mi], &bh[sub*2]);   // hi*hi
                    mma16816(acc[mi][ni], al[mi], &bh[sub*2]);   // lo*hi
                    mma16816(acc[mi][ni], ah[mi], &bl[sub*2]);   // hi*lo
                }
        }
    };

    // ---- prologue ----
    cpB(0, 0); cp_commit();
    issueA(0, 0); combineA(0, 0);
    issueA(0, 1); combineA(0, 1);
    storeA(0);
    cp_wait0();
    __syncthreads();

    // ---- main loop ----
    for (int kt = 0; kt < KTILES; kt++){
        int cur = kt & 1, nxt = cur ^ 1;
        bool pf = (kt + 1 < KTILES);
        if (pf){ cpB(kt + 1, nxt); cp_commit(); issueA(kt + 1, 0); }
        compute_half(cur, 0);
        if (pf){ combineA(kt + 1, 0); issueA(kt + 1, 1); }
        compute_half(cur, 16);
        if (pf){ combineA(kt + 1, 1); storeA(nxt); }
        cp_wait0();
        __syncthreads();
    }

    // ---- epilogue: y = acc + bias, fused per-channel stats ----
    float* yout = (MODE == 0) ? g_y1 : g_y2;
    float* gst  = (MODE == 0) ? g_stats1 : g_stats2;
    #pragma unroll
    for (int ni = 0; ni < 8; ni++){
        int gc = wn*64 + ni*8 + ((lane & 3) << 1);
        float b0 = s_bias[gc], b1 = s_bias[gc+1];
        float sum0 = 0.f, sq0 = 0.f, sum1 = 0.f, sq1 = 0.f;
        #pragma unroll
        for (int mi = 0; mi < 2; mi++){
            int gr = row0 + wm*32 + mi*16 + (lane >> 2);
            float v0 = acc[mi][ni][0] + b0;
            float v1 = acc[mi][ni][1] + b1;
            float v2 = acc[mi][ni][2] + b0;
            float v3 = acc[mi][ni][3] + b1;
            float2 p;
            p.x = v0; p.y = v1;
            *(float2*)(yout + (size_t)gr*CO_ + gc) = p;
            p.x = v2; p.y = v3;
            *(float2*)(yout + (size_t)(gr+8)*CO_ + gc) = p;
            sum0 += v0 + v2;  sq0 = fmaf(v0, v0, fmaf(v2, v2, sq0));
            sum1 += v1 + v3;  sq1 = fmaf(v1, v1, fmaf(v3, v3, sq1));
        }
        atomicAdd(&s_sum[gc],   sum0);
        atomicAdd(&s_sq[gc],    sq0);
        atomicAdd(&s_sum[gc+1], sum1);
        atomicAdd(&s_sq[gc+1],  sq1);
    }
    __syncthreads();
    if (tid < 256){
        atomicAdd(&gst[tid],        s_sum[tid]);
        atomicAdd(&gst[CO_ + tid],  s_sq[tid]);
    }
}

// ---------------- BN finalize ---------------------------------------------
template<int L>
__global__ void bnfin_kernel(const float* __restrict__ g, const float* __restrict__ beta){
    int c = threadIdx.x;
    const float* st = (L == 1) ? g_stats1 : g_stats2;
    float* pa = (L == 1) ? g_bn1a : g_bn2a;
    float* pb = (L == 1) ? g_bn1b : g_bn2b;
    const float invN = 1.f / (float)BNR;
    float mean = st[c] * invN;
    float var  = st[CO_ + c] * invN - mean*mean;
    float a = g[c] / sqrtf(var + 1e-5f);
    pa[c] = a;
    pb[c] = beta[c] - mean*a;
}

// ---------------- BN2 + relu + transpose to (b, c, n) ---------------------
__global__ void out_kernel(float* __restrict__ out){
    __shared__ float s[32][33];
    int b  = blockIdx.z;
    int n0 = blockIdx.x * 32, c0 = blockIdx.y * 32;
    int tx = threadIdx.x, ty = threadIdx.y;
    float v = g_y2[(size_t)(b*N_ + n0 + ty)*CO_ + c0 + tx];
    float a = g_bn2a[c0 + tx], bb = g_bn2b[c0 + tx];
    s[ty][tx] = fmaxf(fmaf(a, v, bb), 0.f);
    __syncthreads();
    out[(size_t)(b*CO_ + c0 + ty)*N_ + n0 + tx] = s[tx][ty];
}

// ---------------- launch ---------------------------------------------------
extern "C" void kernel_launch(void* const* d_in, const int* in_sizes, int n_in,
                              void* d_out, int out_size){
    const float* xyz1    = (const float*)d_in[0];
    const float* xyz2    = (const float*)d_in[1];
    const float* points1 = (const float*)d_in[2];
    const float* points2 = (const float*)d_in[3];
    const float* W1      = (const float*)d_in[4];
    const float* b1      = (const float*)d_in[5];
    const float* g1      = (const float*)d_in[6];
    const float* beta1   = (const float*)d_in[7];
    const float* W2      = (const float*)d_in[8];
    const float* b2      = (const float*)d_in[9];
    const float* g2      = (const float*)d_in[10];
    const float* beta2   = (const float*)d_in[11];
    float* out = (float*)d_out;

    cudaFuncSetAttribute(gemm_kernel<0,24>, cudaFuncAttributeMaxDynamicSharedMemorySize, SMEM_BYTES);
    cudaFuncSetAttribute(gemm_kernel<1,8>,  cudaFuncAttributeMaxDynamicSharedMemorySize, SMEM_BYTES);

    zero_kernel<<<1, 512>>>();
    prep_kernel<<<768, 256>>>(W1, W2);
    three_nn_kernel<<<dim3(16, 16), 256>>>(xyz1, xyz2);

    gemm_kernel<0,24><<<512, 512, SMEM_BYTES>>>(points1, points2, b1);
    bnfin_kernel<1><<<1, 256>>>(g1, beta1);

    gemm_kernel<1,8><<<512, 512, SMEM_BYTES>>>(nullptr, nullptr, b2);
    bnfin_kernel<2><<<1, 256>>>(g2, beta2);

    out_kernel<<<dim3(128, 8, 16), dim3(32, 32)>>>(out);
}